// round 2
// baseline (speedup 1.0000x reference)
#include <cuda_runtime.h>
#include <cuda_fp16.h>

#define B_ 256
#define T_ 100
#define D_ 4096
#define H_ 1024

#define BM 64
#define BN 128
#define BK 32
#define SA 40        // As row stride in halfs (padded: conflict-free ldmatrix)
#define SBN 136      // Bs row stride in halfs (padded: conflict-free ldmatrix.trans)
#define NTH 256
#define SPLITK 4

// Scratch (static __device__ arrays; no dynamic allocation anywhere)
__device__ __align__(16) __half g_KFh[D_ * H_];            // KFinv fp16 [D,H]
__device__ __align__(16) __half g_Zh[H_ * D_];             // Z fp16 [H,D]
__device__ __align__(16) __half g_diffh[B_ * D_];          // x_t - nb_t, fp16
__device__ __align__(16) __half g_hidh[B_ * H_];           // hidden fp16
__device__ __align__(16) float  g_hidpart[SPLITK * B_ * H_]; // split-K partials

__device__ __forceinline__ unsigned smem_u32(const void* p) {
    return (unsigned)__cvta_generic_to_shared(p);
}

__device__ __forceinline__ void mma16816(float* c, const unsigned* a, const unsigned* b) {
    asm volatile(
        "mma.sync.aligned.m16n8k16.row.col.f32.f16.f16.f32 "
        "{%0,%1,%2,%3},{%4,%5,%6,%7},{%8,%9},{%0,%1,%2,%3};\n"
        : "+f"(c[0]), "+f"(c[1]), "+f"(c[2]), "+f"(c[3])
        : "r"(a[0]), "r"(a[1]), "r"(a[2]), "r"(a[3]), "r"(b[0]), "r"(b[1]));
}

__device__ __forceinline__ void ldsm_x4(unsigned addr, unsigned* r) {
    asm volatile("ldmatrix.sync.aligned.m8n8.x4.shared.b16 {%0,%1,%2,%3}, [%4];\n"
        : "=r"(r[0]), "=r"(r[1]), "=r"(r[2]), "=r"(r[3]) : "r"(addr));
}
__device__ __forceinline__ void ldsm_x4_t(unsigned addr, unsigned* r) {
    asm volatile("ldmatrix.sync.aligned.m8n8.x4.trans.shared.b16 {%0,%1,%2,%3}, [%4];\n"
        : "=r"(r[0]), "=r"(r[1]), "=r"(r[2]), "=r"(r[3]) : "r"(addr));
}

// Shared GEMM mainloop: C[BM,BN] += A[m0:,kbase:] * B[kbase:, n0:]
// A row-major [*, lda] fp16, B row-major [*, ldb] fp16 (K-major), fp32 accum.
// 8 warps as 2(m) x 4(n), warp tile 32x32, mma m16n8k16.
// 2-stage smem ping-pong with register prefetch of the next tile.
__device__ __forceinline__ void gemm_tile(
    const __half* __restrict__ Ag, int lda,
    const __half* __restrict__ Bg, int ldb,
    int m0, int n0, int kbase, int iters,
    float (&acc)[2][4][4])
{
    __shared__ __align__(16) __half As[2][BM * SA];
    __shared__ __align__(16) __half Bs[2][BK * SBN];

    const int tid = threadIdx.x;
    const int lane = tid & 31;
    const int wid = tid >> 5;
    const int wm = (wid & 1) * 32;
    const int wn = (wid >> 1) * 32;

    // Global->smem loader mapping
    const int ar = tid >> 2, ac = (tid & 3) * 8;     // A: 64 rows x 4 uint4
    const int br = tid >> 4, bc = (tid & 15) * 8;    // B: rows br and br+16, 16 uint4/row

    const __half* Ap  = Ag + (m0 + ar) * lda + kbase + ac;
    const __half* Bp0 = Bg + (kbase + br) * ldb + n0 + bc;
    const __half* Bp1 = Bg + (kbase + br + 16) * ldb + n0 + bc;

    uint4 a_ld  = *(const uint4*)Ap;
    uint4 b0_ld = *(const uint4*)Bp0;
    uint4 b1_ld = *(const uint4*)Bp1;

    *(uint4*)&As[0][ar * SA + ac]          = a_ld;
    *(uint4*)&Bs[0][br * SBN + bc]         = b0_ld;
    *(uint4*)&Bs[0][(br + 16) * SBN + bc]  = b1_ld;
    __syncthreads();

    // ldmatrix per-lane address components
    const int a_row  = (lane & 7) + ((lane >> 3) & 1) * 8;  // + wm + mf*16
    const int a_colo = (lane >> 4) * 8;                     // + kk
    const int b_rowo = (lane & 7) + ((lane >> 3) & 1) * 8;  // + kk
    const int b_colo = ((lane >> 4) & 1) * 8;               // + wn + nf2*16

    for (int it = 0; it < iters; ++it) {
        const int cur = it & 1;
        if (it + 1 < iters) {
            a_ld  = *(const uint4*)(Ap + (it + 1) * BK);
            b0_ld = *(const uint4*)(Bp0 + (long)(it + 1) * BK * ldb);
            b1_ld = *(const uint4*)(Bp1 + (long)(it + 1) * BK * ldb);
        }
        const __half* Asb = As[cur];
        const __half* Bsb = Bs[cur];
#pragma unroll
        for (int kk = 0; kk < BK; kk += 16) {
            unsigned bf[4][2];
#pragma unroll
            for (int nf2 = 0; nf2 < 2; ++nf2) {
                unsigned r[4];
                unsigned addr = smem_u32(&Bsb[(kk + b_rowo) * SBN + wn + nf2 * 16 + b_colo]);
                ldsm_x4_t(addr, r);
                bf[nf2 * 2][0]     = r[0]; bf[nf2 * 2][1]     = r[1];
                bf[nf2 * 2 + 1][0] = r[2]; bf[nf2 * 2 + 1][1] = r[3];
            }
#pragma unroll
            for (int mf = 0; mf < 2; ++mf) {
                unsigned av[4];
                unsigned addr = smem_u32(&Asb[(wm + mf * 16 + a_row) * SA + kk + a_colo]);
                ldsm_x4(addr, av);
#pragma unroll
                for (int nf = 0; nf < 4; ++nf)
                    mma16816(acc[mf][nf], av, bf[nf]);
            }
        }
        if (it + 1 < iters) {
            const int nxt = cur ^ 1;
            *(uint4*)&As[nxt][ar * SA + ac]         = a_ld;
            *(uint4*)&Bs[nxt][br * SBN + bc]        = b0_ld;
            *(uint4*)&Bs[nxt][(br + 16) * SBN + bc] = b1_ld;
        }
        __syncthreads();
    }
}

// GEMM1 (split-K): partial[z] = diff @ KFinv over K-range z
__global__ void __launch_bounds__(NTH) gemm1_k() {
    float acc[2][4][4];
#pragma unroll
    for (int i = 0; i < 2; ++i)
#pragma unroll
        for (int j = 0; j < 4; ++j)
#pragma unroll
            for (int k = 0; k < 4; ++k) acc[i][j][k] = 0.f;

    const int m0 = blockIdx.y * BM;
    const int n0 = blockIdx.x * BN;
    const int kb = blockIdx.z * (D_ / SPLITK);
    gemm_tile(g_diffh, D_, g_KFh, H_, m0, n0, kb, (D_ / SPLITK) / BK, acc);

    float* out = g_hidpart + blockIdx.z * (B_ * H_);
    const int lane = threadIdx.x & 31, wid = threadIdx.x >> 5;
    const int wm = (wid & 1) * 32, wn = (wid >> 1) * 32;
    const int r = lane >> 2, cp = (lane & 3) * 2;
#pragma unroll
    for (int mf = 0; mf < 2; ++mf)
#pragma unroll
        for (int nf = 0; nf < 4; ++nf) {
            const int m = m0 + wm + mf * 16 + r;
            const int n = n0 + wn + nf * 8 + cp;
            *(float2*)&out[m * H_ + n]       = make_float2(acc[mf][nf][0], acc[mf][nf][1]);
            *(float2*)&out[(m + 8) * H_ + n] = make_float2(acc[mf][nf][2], acc[mf][nf][3]);
        }
}

// Reduce split-K partials + b_hidden -> fp16 hidden
__global__ void reduce_k(const float* __restrict__ bh) {
    const int i = blockIdx.x * blockDim.x + threadIdx.x;
    float s = g_hidpart[i] + g_hidpart[i + B_ * H_]
            + g_hidpart[i + 2 * B_ * H_] + g_hidpart[i + 3 * B_ * H_]
            + bh[i & (H_ - 1)];
    g_hidh[i] = __float2half(s);
}

// GEMM2 + fused epilogue: nb = sigmoid(hidden@Z + b_out); write output;
// also write next step's diff = x[:,t+1,:] - nb (fp16)
__global__ void __launch_bounds__(NTH) gemm2_k(const float* __restrict__ x,
                                               const float* __restrict__ b_out,
                                               float* __restrict__ out, int t) {
    float acc[2][4][4];
#pragma unroll
    for (int i = 0; i < 2; ++i)
#pragma unroll
        for (int j = 0; j < 4; ++j)
#pragma unroll
            for (int k = 0; k < 4; ++k) acc[i][j][k] = 0.f;

    const int m0 = blockIdx.y * BM;
    const int n0 = blockIdx.x * BN;
    gemm_tile(g_hidh, H_, g_Zh, D_, m0, n0, 0, H_ / BK, acc);

    const int lane = threadIdx.x & 31, wid = threadIdx.x >> 5;
    const int wm = (wid & 1) * 32, wn = (wid >> 1) * 32;
    const int r = lane >> 2, cp = (lane & 3) * 2;
    const bool hasnext = (t + 1 < T_);

#pragma unroll
    for (int mf = 0; mf < 2; ++mf)
#pragma unroll
        for (int nf = 0; nf < 4; ++nf) {
            const int n = n0 + wn + nf * 8 + cp;
            const float bo0 = b_out[n], bo1 = b_out[n + 1];
#pragma unroll
            for (int half_m = 0; half_m < 2; ++half_m) {
                const int m = m0 + wm + mf * 16 + r + half_m * 8;
                float v0 = acc[mf][nf][half_m * 2 + 0] + bo0;
                float v1 = acc[mf][nf][half_m * 2 + 1] + bo1;
                v0 = 1.f / (1.f + __expf(-v0));
                v1 = 1.f / (1.f + __expf(-v1));
                *(float2*)&out[m * (T_ * D_) + t * D_ + n] = make_float2(v0, v1);
                if (hasnext) {
                    const float2 xv = *(const float2*)&x[m * (T_ * D_) + (t + 1) * D_ + n];
                    *(__half2*)&g_diffh[m * D_ + n] =
                        __floats2half2_rn(xv.x - v0, xv.y - v1);
                }
            }
        }
}

// One-time fp32 -> fp16 weight conversion
__global__ void convert_k(const float* __restrict__ Z, const float* __restrict__ KF) {
    const int i = blockIdx.x * blockDim.x + threadIdx.x;
    if (i < D_ * H_) {
        g_KFh[i] = __float2half(KF[i]);
        g_Zh[i]  = __float2half(Z[i]);
    }
}

// Step-0 diff: nb0 = b_out broadcast (no sigmoid on step 0, per reference)
__global__ void init_k(const float* __restrict__ x, const float* __restrict__ bo) {
    const int i = blockIdx.x * blockDim.x + threadIdx.x;  // over B_*D_
    const int b = i >> 12;            // D_ = 4096
    const int k = i & (D_ - 1);
    g_diffh[i] = __float2half(x[b * (T_ * D_) + k] - bo[k]);
}

extern "C" void kernel_launch(void* const* d_in, const int* in_sizes, int n_in,
                              void* d_out, int out_size) {
    const float* x  = (const float*)d_in[0];   // [B,T,D]
    const float* Z  = (const float*)d_in[1];   // [H,D]
    const float* bo = (const float*)d_in[2];   // [D]
    const float* KF = (const float*)d_in[3];   // [D,H]
    const float* bh = (const float*)d_in[4];   // [H]
    float* out = (float*)d_out;                // [B,T,D]

    convert_k<<<(D_ * H_ + 255) / 256, 256>>>(Z, KF);
    init_k<<<(B_ * D_ + 255) / 256, 256>>>(x, bo);

    dim3 g1(H_ / BN, B_ / BM, SPLITK);  // (8, 4, 4)
    dim3 g2(D_ / BN, B_ / BM);          // (32, 4)
    for (int t = 0; t < T_; ++t) {
        gemm1_k<<<g1, NTH>>>();
        reduce_k<<<(B_ * H_) / 256, 256>>>(bh);
        gemm2_k<<<g2, NTH>>>(x, bo, out, t);
    }
}